// round 9
// baseline (speedup 1.0000x reference)
#include <cuda_runtime.h>
#include <cuda_bf16.h>
#include <math.h>
#include <stdint.h>

// ============================================================================
// HypHawkes, fp8 tensor-core path (legacy mma.sync; tcgen05 blocked by
// compute_103 lowering).
//
//   K1/K2: row-scale query/context (fused expmap0+project) -> fp8 e4m3 x128
//   K3:    W -> fp8 e4m3 x128
//   K4:    GEMM1 q2 = qs @ wb^T   (m16n8k32 e4m3, fp32 acc, fp8 out x1/128)
//   K5:    GEMM2 scores = q2 @ cs^T (m16n8k32 e4m3, fp32 acc, bf16 out)
//   K6:    row softmax(scores/(d*16384)) + expmap0/project -> out (fp32)
//
// GEMM: CTA 128x128x128B, 3-stage cp.async (96 KB -> 2 CTAs/SM), 8 warps
// (2m x 4n), warp tile 64x32, ldmatrix.x4 fragments (fp8-k32 fragments are
// bit-identical to bf16-k16 fragments in b16-element view), XOR-swizzled smem.
// ============================================================================

#define MAXN 4096
#define MAXD 1024

__device__ uint8_t       g_qs[MAXN * MAXD];
__device__ uint8_t       g_cs[MAXN * MAXD];
__device__ uint8_t       g_wb[MAXD * MAXD];
__device__ uint8_t       g_q2[MAXN * MAXD];
__device__ __nv_bfloat16 g_scores[(size_t)MAXN * MAXN];

#define MIN_NORM 1e-5f
#define PROJ_EPS 4e-3f
#define QSCALE   128.0f     // input quantization scale
#define OSCALE   (1.0f / 128.0f)

// ---------------------------------------------------------------------------
// helpers
// ---------------------------------------------------------------------------
__device__ __forceinline__ uint32_t smem_u32(const void* p) {
    uint32_t a;
    asm("{ .reg .u64 t; cvta.to.shared.u64 t, %1; cvt.u32.u64 %0, t; }"
        : "=r"(a) : "l"(p));
    return a;
}
__device__ __forceinline__ void cp16(uint32_t dst, const void* src) {
    asm volatile("cp.async.cg.shared.global [%0], [%1], 16;" :: "r"(dst), "l"(src));
}
#define CP_COMMIT() asm volatile("cp.async.commit_group;" ::: "memory")
#define CP_WAIT(N)  asm volatile("cp.async.wait_group %0;" :: "n"(N) : "memory")

__device__ __forceinline__ void ldsm_x4(uint32_t* r, uint32_t addr) {
    asm volatile("ldmatrix.sync.aligned.m8n8.x4.shared.b16 {%0,%1,%2,%3}, [%4];"
                 : "=r"(r[0]), "=r"(r[1]), "=r"(r[2]), "=r"(r[3]) : "r"(addr));
}
// fp8 e4m3 MMA: D[16x8] += A[16x32] * B[32x8], fp32 accumulate
__device__ __forceinline__ void mma16832(float* c, const uint32_t* a, const uint32_t* b) {
    asm volatile(
        "mma.sync.aligned.m16n8k32.row.col.f32.e4m3.e4m3.f32 "
        "{%0,%1,%2,%3}, {%4,%5,%6,%7}, {%8,%9}, {%0,%1,%2,%3};\n"
        : "+f"(c[0]), "+f"(c[1]), "+f"(c[2]), "+f"(c[3])
        : "r"(a[0]), "r"(a[1]), "r"(a[2]), "r"(a[3]), "r"(b[0]), "r"(b[1]));
}
// pack two fp32 -> e4m3x2 (byte0 = lo, byte1 = hi)
__device__ __forceinline__ uint16_t f2_e4m3x2(float hi, float lo) {
    uint16_t h;
    asm("cvt.rn.satfinite.e4m3x2.f32 %0, %1, %2;" : "=h"(h) : "f"(hi), "f"(lo));
    return h;
}

// ---------------------------------------------------------------------------
// K1/K2: per-row hyperbolic scale + fp32 -> fp8 (x QSCALE)
// scale = min(tanh(sqrt_c*r), 1-eps)/(sqrt_c*r), r = max(||u||, 1e-5)
// ---------------------------------------------------------------------------
__global__ __launch_bounds__(256)
void scale_rows_fp8_kernel(const float* __restrict__ in, uint8_t* __restrict__ out,
                           const float* __restrict__ c, int d) {
    __shared__ float sh[8];
    const int row = blockIdx.x;
    const int tid = threadIdx.x;
    const float4* r = (const float4*)(in + (size_t)row * d);
    const int d4 = d >> 2;
    float ss = 0.f;
    for (int i = tid; i < d4; i += 256) {
        float4 v = r[i];
        ss = fmaf(v.x, v.x, fmaf(v.y, v.y, fmaf(v.z, v.z, fmaf(v.w, v.w, ss))));
    }
#pragma unroll
    for (int o = 16; o; o >>= 1) ss += __shfl_xor_sync(0xffffffffu, ss, o);
    if ((tid & 31) == 0) sh[tid >> 5] = ss;
    __syncthreads();
    const float tot = sh[0] + sh[1] + sh[2] + sh[3] + sh[4] + sh[5] + sh[6] + sh[7];
    const float sc = sqrtf(c[0]);
    const float rn = fmaxf(sqrtf(tot), MIN_NORM);
    const float t  = fminf(tanhf(sc * rn), 1.0f - PROJ_EPS);
    const float scale = (t / (sc * rn)) * QSCALE;
    uint32_t* o = (uint32_t*)(out + (size_t)row * d);
    for (int i = tid; i < d4; i += 256) {
        float4 v = r[i];
        uint16_t p0 = f2_e4m3x2(v.y * scale, v.x * scale);
        uint16_t p1 = f2_e4m3x2(v.w * scale, v.z * scale);
        o[i] = (uint32_t)p0 | ((uint32_t)p1 << 16);
    }
}

// ---------------------------------------------------------------------------
// K3: fp32 -> fp8 convert (x QSCALE)
// ---------------------------------------------------------------------------
__global__ __launch_bounds__(256)
void convert_w_fp8_kernel(const float4* __restrict__ in, uint32_t* __restrict__ out,
                          int n4) {
    int i = blockIdx.x * blockDim.x + threadIdx.x;
    if (i < n4) {
        float4 v = in[i];
        uint16_t p0 = f2_e4m3x2(v.y * QSCALE, v.x * QSCALE);
        uint16_t p1 = f2_e4m3x2(v.w * QSCALE, v.z * QSCALE);
        out[i] = (uint32_t)p0 | ((uint32_t)p1 << 16);
    }
}

// ---------------------------------------------------------------------------
// fp8 GEMM (TN): C[M,N] = A[M,K] @ B[N,K]^T, e4m3 in, fp32 acc.
// CTA 128x128, K-tile 128 bytes, 3 stages, 96 KB smem, 2 CTAs/SM.
// OUT_FP8: C = acc * OSCALE as e4m3 bytes; else C = acc as bf16.
// ---------------------------------------------------------------------------
#define BM 128
#define BN 128
#define BKB 128                       // K bytes per tile (128 fp8)
#define STG 3
#define A_ST (BM * BKB)               // 16384 B
#define B_ST (BN * BKB)               // 16384 B
#define B_BASE (STG * A_ST)           // 49152
#define GSMEM (B_BASE + STG * B_ST)   // 98304 = 96 KB

extern __shared__ __align__(1024) char dyn_smem[];

template <bool OUT_FP8>
__global__ __launch_bounds__(256, 2)
void gemm_fp8_kernel(const uint8_t* __restrict__ A,
                     const uint8_t* __restrict__ B,
                     void* __restrict__ Cv, int M, int N, int K) {
    const uint32_t sb = smem_u32(dyn_smem);
    const int tid  = threadIdx.x;
    const int wid  = tid >> 5;
    const int lane = tid & 31;
    const int bm = blockIdx.y * BM;
    const int bn = blockIdx.x * BN;
    const int wm = (wid & 1) * 64;    // 2 warps in m
    const int wn = (wid >> 1) * 32;   // 4 warps in n
    const int NK = K / BKB;

    float acc[4][4][4];
#pragma unroll
    for (int i = 0; i < 4; i++)
#pragma unroll
        for (int j = 0; j < 4; j++)
#pragma unroll
            for (int k = 0; k < 4; k++) acc[i][j][k] = 0.f;

    // cp.async staging: rows 128 B = 8 x 16B chunks; swizzle chunk ^= (row&7).
    auto load_stage = [&](int j) {
        const int s = (j % STG);
        const uint32_t ab = sb + s * A_ST;
        const uint32_t bb = sb + B_BASE + s * B_ST;
        const uint8_t* Aj = A + (size_t)bm * K + (size_t)j * BKB;
        const uint8_t* Bj = B + (size_t)bn * K + (size_t)j * BKB;
#pragma unroll
        for (int i = 0; i < 4; ++i) {
            int cid = tid + 256 * i;
            int row = cid >> 3, seg = cid & 7;
            uint32_t off = (uint32_t)(row * 128) + (uint32_t)((seg ^ (row & 7)) * 16);
            cp16(ab + off, Aj + (size_t)row * K + seg * 16);
        }
#pragma unroll
        for (int i = 0; i < 4; ++i) {
            int cid = tid + 256 * i;
            int row = cid >> 3, seg = cid & 7;
            uint32_t off = (uint32_t)(row * 128) + (uint32_t)((seg ^ (row & 7)) * 16);
            cp16(bb + off, Bj + (size_t)row * K + seg * 16);
        }
    };

#pragma unroll
    for (int j = 0; j < STG - 1; ++j) { load_stage(j); CP_COMMIT(); }

    // LDSM addressing (b16-element view; fp8 k32 frag == bf16 k16 frag):
    const int sub  = lane >> 3;   // 0..3
    const int trow = lane & 7;
    const int a_row_l = wm + (sub & 1) * 8 + trow;   // + mi*16
    const int a_kkB   = (sub >> 1) * 16;             // byte col within k-step
    const int b_row_l = wn + (sub >> 1) * 8 + trow;  // + pi*16
    const int b_kkB   = (sub & 1) * 16;
    const uint32_t sw = (uint32_t)trow << 4;         // XOR swizzle bytes [6:4]

    for (int kt = 0; kt < NK; ++kt) {
        CP_WAIT(1);
        __syncthreads();
        const int jn = kt + STG - 1;
        if (jn < NK) load_stage(jn);
        CP_COMMIT();

        const int s = kt % STG;
        const uint32_t abase = sb + s * A_ST;
        const uint32_t bbase = sb + B_BASE + s * B_ST;

#pragma unroll
        for (int ks = 0; ks < 4; ++ks) {           // 4 x k32 per 128B tile
            const int k0 = ks * 32;                // byte offset
            uint32_t af[4][4], bf[2][4];
#pragma unroll
            for (int mi = 0; mi < 4; ++mi) {
                uint32_t col = (uint32_t)(k0 + a_kkB) ^ sw;
                ldsm_x4(af[mi], abase + (uint32_t)((a_row_l + mi * 16) * 128) + col);
            }
#pragma unroll
            for (int pi = 0; pi < 2; ++pi) {
                uint32_t col = (uint32_t)(k0 + b_kkB) ^ sw;
                ldsm_x4(bf[pi], bbase + (uint32_t)((b_row_l + pi * 16) * 128) + col);
            }
#pragma unroll
            for (int mi = 0; mi < 4; ++mi)
#pragma unroll
                for (int ni = 0; ni < 4; ++ni)
                    mma16832(acc[mi][ni], af[mi], &bf[ni >> 1][(ni & 1) * 2]);
        }
    }

    // epilogue: thread holds (row,col..col+1) = c0,c1 and (row+8,...) = c2,c3
    const int g  = lane >> 2;
    const int tg = lane & 3;
    if (OUT_FP8) {
        uint8_t* C = (uint8_t*)Cv;
#pragma unroll
        for (int mi = 0; mi < 4; ++mi) {
            const int row = bm + wm + mi * 16 + g;
#pragma unroll
            for (int ni = 0; ni < 4; ++ni) {
                const int col = bn + wn + ni * 8 + tg * 2;
                *(uint16_t*)&C[(size_t)row * N + col] =
                    f2_e4m3x2(acc[mi][ni][1] * OSCALE, acc[mi][ni][0] * OSCALE);
                *(uint16_t*)&C[(size_t)(row + 8) * N + col] =
                    f2_e4m3x2(acc[mi][ni][3] * OSCALE, acc[mi][ni][2] * OSCALE);
            }
        }
    } else {
        __nv_bfloat16* C = (__nv_bfloat16*)Cv;
#pragma unroll
        for (int mi = 0; mi < 4; ++mi) {
            const int row = bm + wm + mi * 16 + g;
#pragma unroll
            for (int ni = 0; ni < 4; ++ni) {
                const int col = bn + wn + ni * 8 + tg * 2;
                *(__nv_bfloat162*)&C[(size_t)row * N + col] =
                    __floats2bfloat162_rn(acc[mi][ni][0], acc[mi][ni][1]);
                *(__nv_bfloat162*)&C[(size_t)(row + 8) * N + col] =
                    __floats2bfloat162_rn(acc[mi][ni][2], acc[mi][ni][3]);
            }
        }
    }
}

// ---------------------------------------------------------------------------
// K6: row softmax(scores * inv_d) fused with expmap0+project (bf16 scores in).
// inv_d folds the fp8 scale: logits = raw/(d * QSCALE^2).
// ---------------------------------------------------------------------------
__global__ __launch_bounds__(256)
void softmax_proj_kernel(const __nv_bfloat16* __restrict__ S, float* __restrict__ out,
                         const float* __restrict__ c, int m, float inv_d) {
    __shared__ float sh[16];
    const int row = blockIdx.x;
    const int tid = threadIdx.x;

    const uint4* sv = (const uint4*)(S + (size_t)row * m) + tid * 2;
    uint4 u0 = sv[0], u1 = sv[1];
    float v[16];
    {
        const uint32_t* w = (const uint32_t*)&u0;
#pragma unroll
        for (int i = 0; i < 4; ++i) {
            __nv_bfloat162 h = *(__nv_bfloat162*)&w[i];
            v[2 * i]     = __bfloat162float(h.x);
            v[2 * i + 1] = __bfloat162float(h.y);
        }
        const uint32_t* w2 = (const uint32_t*)&u1;
#pragma unroll
        for (int i = 0; i < 4; ++i) {
            __nv_bfloat162 h = *(__nv_bfloat162*)&w2[i];
            v[8 + 2 * i]     = __bfloat162float(h.x);
            v[8 + 2 * i + 1] = __bfloat162float(h.y);
        }
    }

    float vmax = v[0];
#pragma unroll
    for (int i = 1; i < 16; ++i) vmax = fmaxf(vmax, v[i]);
#pragma unroll
    for (int o = 16; o; o >>= 1) vmax = fmaxf(vmax, __shfl_xor_sync(0xffffffffu, vmax, o));
    if ((tid & 31) == 0) sh[tid >> 5] = vmax;
    __syncthreads();
    const float rmax = fmaxf(fmaxf(fmaxf(sh[0], sh[1]), fmaxf(sh[2], sh[3])),
                             fmaxf(fmaxf(sh[4], sh[5]), fmaxf(sh[6], sh[7])));
    __syncthreads();

    float es = 0.f, e2 = 0.f;
#pragma unroll
    for (int i = 0; i < 16; ++i) {
        float e = __expf((v[i] - rmax) * inv_d);
        v[i] = e;
        es += e;
        e2 = fmaf(e, e, e2);
    }
#pragma unroll
    for (int o = 16; o; o >>= 1) {
        es += __shfl_xor_sync(0xffffffffu, es, o);
        e2 += __shfl_xor_sync(0xffffffffu, e2, o);
    }
    if ((tid & 31) == 0) { sh[tid >> 5] = es; sh[8 + (tid >> 5)] = e2; }
    __syncthreads();
    const float tes = sh[0] + sh[1] + sh[2] + sh[3] + sh[4] + sh[5] + sh[6] + sh[7];
    const float te2 = sh[8] + sh[9] + sh[10] + sh[11] + sh[12] + sh[13] + sh[14] + sh[15];

    const float inv = 1.f / tes;
    const float rn  = fmaxf(sqrtf(te2) * inv, MIN_NORM);
    const float sc  = sqrtf(c[0]);
    const float t   = fminf(tanhf(sc * rn), 1.0f - PROJ_EPS);
    const float scale = (t / (sc * rn)) * inv;

    float4* o = (float4*)(out + (size_t)row * m) + tid * 4;
#pragma unroll
    for (int i = 0; i < 4; ++i)
        o[i] = make_float4(v[4 * i] * scale, v[4 * i + 1] * scale,
                           v[4 * i + 2] * scale, v[4 * i + 3] * scale);
}

// ---------------------------------------------------------------------------
// kernel_launch: inputs: query[n,d], context[m,d], W[d,d], c[1]
// ---------------------------------------------------------------------------
extern "C" void kernel_launch(void* const* d_in, const int* in_sizes, int n_in,
                              void* d_out, int out_size) {
    const float* query   = (const float*)d_in[0];
    const float* context = (const float*)d_in[1];
    const float* W       = (const float*)d_in[2];
    const float* c       = (const float*)d_in[3];

    const int d = (int)(sqrt((double)in_sizes[2]) + 0.5);
    const int n = in_sizes[0] / d;
    const int m = in_sizes[1] / d;

    uint8_t *qs, *cs, *wb, *q2;
    __nv_bfloat16* sco;
    cudaGetSymbolAddress((void**)&qs,  g_qs);
    cudaGetSymbolAddress((void**)&cs,  g_cs);
    cudaGetSymbolAddress((void**)&wb,  g_wb);
    cudaGetSymbolAddress((void**)&q2,  g_q2);
    cudaGetSymbolAddress((void**)&sco, g_scores);

    cudaFuncSetAttribute(gemm_fp8_kernel<true>,
                         cudaFuncAttributeMaxDynamicSharedMemorySize, GSMEM);
    cudaFuncSetAttribute(gemm_fp8_kernel<false>,
                         cudaFuncAttributeMaxDynamicSharedMemorySize, GSMEM);

    // K1/K2: hyperbolic row scaling -> fp8 (x128)
    scale_rows_fp8_kernel<<<n, 256>>>(query, qs, c, d);
    scale_rows_fp8_kernel<<<m, 256>>>(context, cs, c, d);

    // K3: W -> fp8 (x128)
    const int n4 = (d * d) / 4;
    convert_w_fp8_kernel<<<(n4 + 255) / 256, 256>>>((const float4*)W, (uint32_t*)wb, n4);

    // K4: q2 = qs @ wb^T  (fp8 out, x1/128 -> q2 = actual*128)
    gemm_fp8_kernel<true><<<dim3(d / BN, n / BM), 256, GSMEM>>>(qs, wb, (void*)q2, n, d, d);

    // K5: scores = q2 @ cs^T  (bf16 out, = actual*16384)
    gemm_fp8_kernel<false><<<dim3(m / BN, n / BM), 256, GSMEM>>>(q2, cs, (void*)sco, n, m, d);

    // K6: softmax(scores/(d*QSCALE^2)) + expmap0/project -> out (fp32)
    softmax_proj_kernel<<<n, 256>>>(sco, (float*)d_out, c, m,
                                    1.0f / ((float)d * QSCALE * QSCALE));
}

// round 10
// speedup vs baseline: 1.1489x; 1.1489x over previous
#include <cuda_runtime.h>
#include <cuda_bf16.h>
#include <math.h>
#include <stdint.h>

// ============================================================================
// HypHawkes (bf16 legacy-HMMA path; tcgen05 blocked by compute_103 lowering,
// fp8 legacy mma.sync measured slower than bf16 on this chip).
//
//   K1/K2: row-scale query/context (fused expmap0+project scalar) -> bf16
//   K3:    W -> bf16
//   K4:    GEMM1 q2[n,d] = qs @ wb^T      (mma.sync bf16, bf16 out)
//   K5:    GEMM2 scores[n,m] = q2 @ cs^T  (mma.sync bf16, bf16 out)
//   K6:    row softmax(scores/d) + expmap0/project -> out (fp32)
//
// GEMM: CTA 128x128x64, 3-stage cp.async (96 KB -> 2 CTAs/SM), 8 warps
// (2m x 4n), warp tile 64x32, ldmatrix.x4 fragments, XOR-swizzled smem.
// NEW vs round 8: register-level software pipelining of LDSM fragments —
// next k-step's A/B fragments are fetched interleaved with current k-step's
// MMAs, so the tensor pipe is not starved during fragment-load bursts.
// ============================================================================

#define MAXN 4096
#define MAXD 1024

__device__ __nv_bfloat16 g_qs[MAXN * MAXD];
__device__ __nv_bfloat16 g_cs[MAXN * MAXD];
__device__ __nv_bfloat16 g_wb[MAXD * MAXD];
__device__ __nv_bfloat16 g_q2[MAXN * MAXD];
__device__ __nv_bfloat16 g_scores[(size_t)MAXN * MAXN];

#define MIN_NORM 1e-5f
#define PROJ_EPS 4e-3f

// ---------------------------------------------------------------------------
// helpers
// ---------------------------------------------------------------------------
__device__ __forceinline__ uint32_t smem_u32(const void* p) {
    uint32_t a;
    asm("{ .reg .u64 t; cvta.to.shared.u64 t, %1; cvt.u32.u64 %0, t; }"
        : "=r"(a) : "l"(p));
    return a;
}
__device__ __forceinline__ void cp16(uint32_t dst, const void* src) {
    asm volatile("cp.async.cg.shared.global [%0], [%1], 16;" :: "r"(dst), "l"(src));
}
#define CP_COMMIT() asm volatile("cp.async.commit_group;" ::: "memory")
#define CP_WAIT(N)  asm volatile("cp.async.wait_group %0;" :: "n"(N) : "memory")

__device__ __forceinline__ void ldsm_x4(uint32_t* r, uint32_t addr) {
    asm volatile("ldmatrix.sync.aligned.m8n8.x4.shared.b16 {%0,%1,%2,%3}, [%4];"
                 : "=r"(r[0]), "=r"(r[1]), "=r"(r[2]), "=r"(r[3]) : "r"(addr));
}
__device__ __forceinline__ void mma16816(float* c, const uint32_t* a, const uint32_t* b) {
    asm volatile(
        "mma.sync.aligned.m16n8k16.row.col.f32.bf16.bf16.f32 "
        "{%0,%1,%2,%3}, {%4,%5,%6,%7}, {%8,%9}, {%0,%1,%2,%3};\n"
        : "+f"(c[0]), "+f"(c[1]), "+f"(c[2]), "+f"(c[3])
        : "r"(a[0]), "r"(a[1]), "r"(a[2]), "r"(a[3]), "r"(b[0]), "r"(b[1]));
}

// ---------------------------------------------------------------------------
// K1/K2: per-row hyperbolic scale + fp32->bf16
// scale = min(tanh(sqrt_c*r), 1-eps)/(sqrt_c*r), r = max(||u||, 1e-5)
// ---------------------------------------------------------------------------
__global__ __launch_bounds__(256)
void scale_rows_kernel(const float* __restrict__ in, __nv_bfloat16* __restrict__ out,
                       const float* __restrict__ c, int d) {
    __shared__ float sh[8];
    const int row = blockIdx.x;
    const float* r = in + (size_t)row * d;
    float ss = 0.f;
    for (int i = threadIdx.x; i < d; i += 256) { float v = r[i]; ss = fmaf(v, v, ss); }
#pragma unroll
    for (int o = 16; o; o >>= 1) ss += __shfl_xor_sync(0xffffffffu, ss, o);
    if ((threadIdx.x & 31) == 0) sh[threadIdx.x >> 5] = ss;
    __syncthreads();
    const float tot = sh[0] + sh[1] + sh[2] + sh[3] + sh[4] + sh[5] + sh[6] + sh[7];
    const float sc = sqrtf(c[0]);
    const float rn = fmaxf(sqrtf(tot), MIN_NORM);
    const float t  = fminf(tanhf(sc * rn), 1.0f - PROJ_EPS);
    const float scale = t / (sc * rn);
    __nv_bfloat16* o = out + (size_t)row * d;
    for (int i = threadIdx.x; i < d; i += 256) o[i] = __float2bfloat16(r[i] * scale);
}

// ---------------------------------------------------------------------------
// K3: fp32 -> bf16 convert
// ---------------------------------------------------------------------------
__global__ __launch_bounds__(256)
void convert_w_kernel(const float4* __restrict__ in, __nv_bfloat162* __restrict__ out,
                      int n4) {
    int i = blockIdx.x * blockDim.x + threadIdx.x;
    if (i < n4) {
        float4 v = in[i];
        out[2 * i]     = __floats2bfloat162_rn(v.x, v.y);
        out[2 * i + 1] = __floats2bfloat162_rn(v.z, v.w);
    }
}

// ---------------------------------------------------------------------------
// GEMM (TN): C[M,N] = A[M,K] @ B[N,K]^T, bf16 in, fp32 acc, bf16 out.
// ---------------------------------------------------------------------------
#define BM 128
#define BN 128
#define BK 64
#define STG 3
#define A_ST (BM * BK * 2)            // 16384 B
#define B_ST (BN * BK * 2)            // 16384 B
#define B_BASE (STG * A_ST)           // 49152
#define GSMEM (B_BASE + STG * B_ST)   // 98304 = 96 KB

extern __shared__ __align__(1024) char dyn_smem[];

__global__ __launch_bounds__(256, 2)
void gemm_bf16_kernel(const __nv_bfloat16* __restrict__ A,
                      const __nv_bfloat16* __restrict__ B,
                      __nv_bfloat16* __restrict__ C, int M, int N, int K) {
    const uint32_t sb = smem_u32(dyn_smem);
    const int tid  = threadIdx.x;
    const int wid  = tid >> 5;
    const int lane = tid & 31;
    const int bm = blockIdx.y * BM;
    const int bn = blockIdx.x * BN;
    const int wm = (wid & 1) * 64;    // 2 warps in m
    const int wn = (wid >> 1) * 32;   // 4 warps in n
    const int NK = K / BK;

    float acc[4][4][4];
#pragma unroll
    for (int i = 0; i < 4; i++)
#pragma unroll
        for (int j = 0; j < 4; j++)
#pragma unroll
            for (int k = 0; k < 4; k++) acc[i][j][k] = 0.f;

    // cp.async staging: rows 128B (64 bf16) = 8 x 16B chunks; chunk ^= (row&7)
    auto load_stage = [&](int j) {
        const int s = (j % STG);
        const uint32_t ab = sb + s * A_ST;
        const uint32_t bb = sb + B_BASE + s * B_ST;
        const __nv_bfloat16* Aj = A + (size_t)bm * K + (size_t)j * BK;
        const __nv_bfloat16* Bj = B + (size_t)bn * K + (size_t)j * BK;
#pragma unroll
        for (int i = 0; i < 4; ++i) {
            int cid = tid + 256 * i;
            int row = cid >> 3, seg = cid & 7;
            uint32_t off = (uint32_t)(row * 128) + (uint32_t)((seg ^ (row & 7)) * 16);
            cp16(ab + off, Aj + (size_t)row * K + seg * 8);
        }
#pragma unroll
        for (int i = 0; i < 4; ++i) {
            int cid = tid + 256 * i;
            int row = cid >> 3, seg = cid & 7;
            uint32_t off = (uint32_t)(row * 128) + (uint32_t)((seg ^ (row & 7)) * 16);
            cp16(bb + off, Bj + (size_t)row * K + seg * 8);
        }
    };

    // prologue: stages 0..1
#pragma unroll
    for (int j = 0; j < STG - 1; ++j) { load_stage(j); CP_COMMIT(); }

    // per-thread LDSM address components (validated in round 8)
    const int sub  = lane >> 3;   // 0..3
    const int trow = lane & 7;
    const int a_row_l = wm + (sub & 1) * 8 + trow;   // + mi*16
    const int a_kk    = (sub >> 1) * 8;              // element col within k-step
    const int b_row_l = wn + (sub >> 1) * 8 + trow;  // + pi*16
    const int b_kk    = (sub & 1) * 8;
    const uint32_t sw = (uint32_t)trow << 4;         // XOR swizzle bytes [6:4]

    for (int kt = 0; kt < NK; ++kt) {
        CP_WAIT(1);
        __syncthreads();
        const int jn = kt + STG - 1;
        if (jn < NK) load_stage(jn);
        CP_COMMIT();

        const int s = kt % STG;
        const uint32_t abase = sb + s * A_ST;
        const uint32_t bbase = sb + B_BASE + s * B_ST;

        // fragment register pipeline: af double-buffered per mi-step,
        // bf cur/next per ks-step.
        uint32_t af[2][4], bfc[2][4], bfn[2][4];

        // tile prologue: ks=0 B fragments + (ks=0, mi=0) A fragment
        ldsm_x4(bfc[0], bbase + (uint32_t)(b_row_l * 128)
                        + ((uint32_t)(b_kk * 2) ^ sw));
        ldsm_x4(bfc[1], bbase + (uint32_t)((b_row_l + 16) * 128)
                        + ((uint32_t)(b_kk * 2) ^ sw));
        ldsm_x4(af[0],  abase + (uint32_t)(a_row_l * 128)
                        + ((uint32_t)(a_kk * 2) ^ sw));

#pragma unroll
        for (int ks = 0; ks < 4; ++ks) {
            const int k0 = ks * 16;
            const int k1 = (ks + 1) * 16;
#pragma unroll
            for (int mi = 0; mi < 4; ++mi) {
                const int cur = mi & 1, nxt = cur ^ 1;
                // prefetch next A fragment (next mi, or next ks's mi=0)
                if (mi < 3) {
                    ldsm_x4(af[nxt], abase + (uint32_t)((a_row_l + (mi + 1) * 16) * 128)
                                     + ((uint32_t)((k0 + a_kk) * 2) ^ sw));
                } else if (ks < 3) {
                    ldsm_x4(af[nxt], abase + (uint32_t)(a_row_l * 128)
                                     + ((uint32_t)((k1 + a_kk) * 2) ^ sw));
                }
                // prefetch next ks's B fragments, spread over mi=0,1
                if (mi == 0 && ks < 3)
                    ldsm_x4(bfn[0], bbase + (uint32_t)(b_row_l * 128)
                                    + ((uint32_t)((k1 + b_kk) * 2) ^ sw));
                if (mi == 1 && ks < 3)
                    ldsm_x4(bfn[1], bbase + (uint32_t)((b_row_l + 16) * 128)
                                    + ((uint32_t)((k1 + b_kk) * 2) ^ sw));
#pragma unroll
                for (int ni = 0; ni < 4; ++ni)
                    mma16816(acc[mi][ni], af[cur], &bfc[ni >> 1][(ni & 1) * 2]);
            }
            if (ks < 3) {
#pragma unroll
                for (int q = 0; q < 4; ++q) { bfc[0][q] = bfn[0][q]; bfc[1][q] = bfn[1][q]; }
            }
        }
    }

    // epilogue: c0/c1 at (row, col..col+1), c2/c3 at (row+8, ...)
    const int g  = lane >> 2;
    const int tg = lane & 3;
#pragma unroll
    for (int mi = 0; mi < 4; ++mi) {
        const int row = bm + wm + mi * 16 + g;
#pragma unroll
        for (int ni = 0; ni < 4; ++ni) {
            const int col = bn + wn + ni * 8 + tg * 2;
            *(__nv_bfloat162*)&C[(size_t)row * N + col] =
                __floats2bfloat162_rn(acc[mi][ni][0], acc[mi][ni][1]);
            *(__nv_bfloat162*)&C[(size_t)(row + 8) * N + col] =
                __floats2bfloat162_rn(acc[mi][ni][2], acc[mi][ni][3]);
        }
    }
}

// ---------------------------------------------------------------------------
// K6: row softmax(scores * inv_d) fused with expmap0+project (bf16 scores in).
// ---------------------------------------------------------------------------
__global__ __launch_bounds__(256)
void softmax_proj_kernel(const __nv_bfloat16* __restrict__ S, float* __restrict__ out,
                         const float* __restrict__ c, int m, float inv_d) {
    __shared__ float sh[16];
    const int row = blockIdx.x;
    const int tid = threadIdx.x;

    const uint4* sv = (const uint4*)(S + (size_t)row * m) + tid * 2;
    uint4 u0 = sv[0], u1 = sv[1];
    float v[16];
    {
        const uint32_t* w = (const uint32_t*)&u0;
#pragma unroll
        for (int i = 0; i < 4; ++i) {
            __nv_bfloat162 h = *(__nv_bfloat162*)&w[i];
            v[2 * i]     = __bfloat162float(h.x);
            v[2 * i + 1] = __bfloat162float(h.y);
        }
        const uint32_t* w2 = (const uint32_t*)&u1;
#pragma unroll
        for (int i = 0; i < 4; ++i) {
            __nv_bfloat162 h = *(__nv_bfloat162*)&w2[i];
            v[8 + 2 * i]     = __bfloat162float(h.x);
            v[8 + 2 * i + 1] = __bfloat162float(h.y);
        }
    }

    float vmax = v[0];
#pragma unroll
    for (int i = 1; i < 16; ++i) vmax = fmaxf(vmax, v[i]);
#pragma unroll
    for (int o = 16; o; o >>= 1) vmax = fmaxf(vmax, __shfl_xor_sync(0xffffffffu, vmax, o));
    if ((tid & 31) == 0) sh[tid >> 5] = vmax;
    __syncthreads();
    const float rmax = fmaxf(fmaxf(fmaxf(sh[0], sh[1]), fmaxf(sh[2], sh[3])),
                             fmaxf(fmaxf(sh[4], sh[5]), fmaxf(sh[6], sh[7])));
    __syncthreads();

    float es = 0.f, e2 = 0.f;
#pragma unroll
    for (int i = 0; i < 16; ++i) {
        float e = __expf((v[i] - rmax) * inv_d);
        v[i] = e;
        es += e;
        e2 = fmaf(e, e, e2);
    }
#pragma unroll
    for (int o = 16; o; o >>= 1) {
        es += __shfl_xor_sync(0xffffffffu, es, o);
        e2 += __shfl_xor_sync(0xffffffffu, e2, o);
    }
    if ((tid & 31) == 0) { sh[tid >> 5] = es; sh[8 + (tid >> 5)] = e2; }
    __syncthreads();
    const float tes = sh[0] + sh[1] + sh[2] + sh[3] + sh[4] + sh[5] + sh[6] + sh[7];
    const float te2 = sh[8] + sh[9] + sh[10] + sh[11] + sh[12] + sh[13] + sh[14] + sh[15];

    const float inv = 1.f / tes;
    const float rn  = fmaxf(sqrtf(te2) * inv, MIN_NORM);
    const float sc  = sqrtf(c[0]);
    const float t   = fminf(tanhf(sc * rn), 1.0f - PROJ_EPS);
    const float scale = (t / (sc * rn)) * inv;

    float4* o = (float4*)(out + (size_t)row * m) + tid * 4;
#pragma unroll
    for (int i = 0; i < 4; ++i)
        o[i] = make_float4(v[4 * i] * scale, v[4 * i + 1] * scale,
                           v[4 * i + 2] * scale, v[4 * i + 3] * scale);
}

// ---------------------------------------------------------------------------
// kernel_launch: inputs: query[n,d], context[m,d], W[d,d], c[1]
// ---------------------------------------------------------------------------
extern "C" void kernel_launch(void* const* d_in, const int* in_sizes, int n_in,
                              void* d_out, int out_size) {
    const float* query   = (const float*)d_in[0];
    const float* context = (const float*)d_in[1];
    const float* W       = (const float*)d_in[2];
    const float* c       = (const float*)d_in[3];

    const int d = (int)(sqrt((double)in_sizes[2]) + 0.5);
    const int n = in_sizes[0] / d;
    const int m = in_sizes[1] / d;

    __nv_bfloat16 *qs, *cs, *wb, *q2, *sco;
    cudaGetSymbolAddress((void**)&qs,  g_qs);
    cudaGetSymbolAddress((void**)&cs,  g_cs);
    cudaGetSymbolAddress((void**)&wb,  g_wb);
    cudaGetSymbolAddress((void**)&q2,  g_q2);
    cudaGetSymbolAddress((void**)&sco, g_scores);

    cudaFuncSetAttribute(gemm_bf16_kernel,
                         cudaFuncAttributeMaxDynamicSharedMemorySize, GSMEM);

    // K1/K2: hyperbolic row scaling -> bf16
    scale_rows_kernel<<<n, 256>>>(query, qs, c, d);
    scale_rows_kernel<<<m, 256>>>(context, cs, c, d);

    // K3: W -> bf16
    const int n4 = (d * d) / 4;
    convert_w_kernel<<<(n4 + 255) / 256, 256>>>((const float4*)W, (__nv_bfloat162*)wb, n4);

    // K4: q2[n,d] = qs @ wb^T
    gemm_bf16_kernel<<<dim3(d / BN, n / BM), 256, GSMEM>>>(qs, wb, q2, n, d, d);

    // K5: scores[n,m] = q2 @ cs^T (bf16 out; logits are scores/1024, bf16-safe)
    gemm_bf16_kernel<<<dim3(m / BN, n / BM), 256, GSMEM>>>(q2, cs, sco, n, m, d);

    // K6: softmax(scores/d) + expmap0/project -> out (fp32)
    softmax_proj_kernel<<<n, 256>>>(sco, (float*)d_out, c, m, 1.0f / (float)d);
}